// round 3
// baseline (speedup 1.0000x reference)
#include <cuda_runtime.h>

// 12 counters: [0..3] = count(pred==c), [4..7] = count(label==c), [8..11] = count(pred==label==c)
__device__ unsigned int g_counts[12];

__global__ void zero_counts_kernel() {
    if (threadIdx.x < 12) g_counts[threadIdx.x] = 0;
}

__global__ __launch_bounds__(256) void iou_count_kernel(
    const float4* __restrict__ preds4,
    const int4*  __restrict__ labels4,
    long long n4,
    const float* __restrict__ preds,
    const int*  __restrict__ labels,
    long long n)
{
    const long long tid    = (long long)blockIdx.x * blockDim.x + threadIdx.x;
    const long long stride = (long long)gridDim.x * blockDim.x;

    // full-width per-class counters
    unsigned int fp[4] = {0u,0u,0u,0u};
    unsigned int fl[4] = {0u,0u,0u,0u};
    unsigned int fe[4] = {0u,0u,0u,0u};
    // packed 8-bit-per-class accumulators
    unsigned int ap = 0u, al = 0u, ae = 0u;
    int pend = 0;

#define FLUSH_PACKED() do {                                   \
        _Pragma("unroll")                                     \
        for (int c = 0; c < 4; c++) {                         \
            fp[c] += (ap >> (8*c)) & 0xFFu;                   \
            fl[c] += (al >> (8*c)) & 0xFFu;                   \
            fe[c] += (ae >> (8*c)) & 0xFFu;                   \
        }                                                     \
        ap = 0u; al = 0u; ae = 0u; pend = 0;                  \
    } while (0)

    #pragma unroll 4
    for (long long i = tid; i < n4; i += stride) {
        float4 pv = preds4[i];
        int4   lv = labels4[i];
        int p0 = (int)pv.x, p1 = (int)pv.y, p2 = (int)pv.z, p3 = (int)pv.w;

        ap += (1u << (p0 << 3)) + (1u << (p1 << 3))
            + (1u << (p2 << 3)) + (1u << (p3 << 3));
        al += (1u << (lv.x << 3)) + (1u << (lv.y << 3))
            + (1u << (lv.z << 3)) + (1u << (lv.w << 3));
        ae += (p0 == lv.x ? (1u << (p0 << 3)) : 0u)
            + (p1 == lv.y ? (1u << (p1 << 3)) : 0u)
            + (p2 == lv.z ? (1u << (p2 << 3)) : 0u)
            + (p3 == lv.w ? (1u << (p3 << 3)) : 0u);

        // each iter adds at most 4 to an 8-bit field; 48 iters -> max 192 < 256
        if (++pend >= 48) FLUSH_PACKED();
    }
    FLUSH_PACKED();

    // scalar tail (n not multiple of 4)
    for (long long i = n4 * 4 + tid; i < n; i += stride) {
        int p = (int)preds[i];
        int l = labels[i];
        fp[p] += 1u;
        fl[l] += 1u;
        if (p == l) fe[p] += 1u;
    }

    // warp-level reduction of the 12 counters
    #pragma unroll
    for (int off = 16; off > 0; off >>= 1) {
        #pragma unroll
        for (int c = 0; c < 4; c++) {
            fp[c] += __shfl_down_sync(0xFFFFFFFFu, fp[c], off);
            fl[c] += __shfl_down_sync(0xFFFFFFFFu, fl[c], off);
            fe[c] += __shfl_down_sync(0xFFFFFFFFu, fe[c], off);
        }
    }

    __shared__ unsigned int s[12];
    if (threadIdx.x < 12) s[threadIdx.x] = 0u;
    __syncthreads();

    if ((threadIdx.x & 31) == 0) {
        #pragma unroll
        for (int c = 0; c < 4; c++) {
            atomicAdd(&s[c],     fp[c]);
            atomicAdd(&s[4 + c], fl[c]);
            atomicAdd(&s[8 + c], fe[c]);
        }
    }
    __syncthreads();

    if (threadIdx.x < 12) atomicAdd(&g_counts[threadIdx.x], s[threadIdx.x]);
#undef FLUSH_PACKED
}

__global__ void iou_finalize_kernel(float* __restrict__ out) {
    int c = threadIdx.x;
    if (c < 4) {
        float inter = (float)g_counts[8 + c];
        float uni   = (float)g_counts[c] + (float)g_counts[4 + c] - inter;
        float iou   = (uni == 0.0f) ? 1.0f : (inter / uni);
        out[c] = 1.0f - 100.0f * iou;
    }
}

extern "C" void kernel_launch(void* const* d_in, const int* in_sizes, int n_in,
                              void* d_out, int out_size)
{
    const float* preds  = (const float*)d_in[0];
    const int*   labels = (const int*)d_in[1];
    float*       out    = (float*)d_out;

    long long n  = (long long)in_sizes[0];
    long long n4 = n >> 2;

    zero_counts_kernel<<<1, 32>>>();

    const int threads = 256;
    const int blocks  = 1024;   // 262144 threads -> 16 float4 iters each at n=16.7M
    iou_count_kernel<<<blocks, threads>>>(
        (const float4*)preds, (const int4*)labels, n4, preds, labels, n);

    iou_finalize_kernel<<<1, 32>>>(out);
}

// round 5
// speedup vs baseline: 1.0462x; 1.0462x over previous
#include <cuda_runtime.h>

#define NBLK 2048
#define NTHR 256

// Per-block partials, SoA: g_partials[c*NBLK + block] for c in 0..11
// [0..3] = count(pred==c), [4..7] = count(label==c), [8..11] = count(pred==label==c)
__device__ unsigned int g_partials[12 * NBLK];
__device__ unsigned int g_ticket;   // zero-initialized at module load; reset by last block

__global__ __launch_bounds__(NTHR) void iou_fused_kernel(
    const float4* __restrict__ preds4,
    const int4*   __restrict__ labels4,
    long long n4,
    const float*  __restrict__ preds,
    const int*    __restrict__ labels,
    long long n,
    float* __restrict__ out)
{
    const long long tid    = (long long)blockIdx.x * NTHR + threadIdx.x;
    const long long stride = (long long)NBLK * NTHR;

    // Full-width counters — only ever indexed with compile-time constants.
    unsigned int fp[4] = {0u,0u,0u,0u};
    unsigned int fl[4] = {0u,0u,0u,0u};
    unsigned int fe[4] = {0u,0u,0u,0u};

    long long i = tid;

    // ---- Batched mainloop: 8 grid-stride iters per batch, loads fully hoisted ----
    for (; i + 7 * stride < n4; i += 8 * stride) {
        float4 pv[8];
        int4   lv[8];
        #pragma unroll
        for (int u = 0; u < 8; u++) pv[u] = __ldcg(&preds4[i + u * stride]);
        #pragma unroll
        for (int u = 0; u < 8; u++) lv[u] = __ldcg(&labels4[i + u * stride]);

        unsigned int ap = 0u, al = 0u, ae = 0u;  // 8-bit packed per-class accumulators
        #pragma unroll
        for (int u = 0; u < 8; u++) {
            int p0 = (int)pv[u].x, p1 = (int)pv[u].y,
                p2 = (int)pv[u].z, p3 = (int)pv[u].w;
            ap += (1u << (p0 << 3)) + (1u << (p1 << 3))
                + (1u << (p2 << 3)) + (1u << (p3 << 3));
            al += (1u << (lv[u].x << 3)) + (1u << (lv[u].y << 3))
                + (1u << (lv[u].z << 3)) + (1u << (lv[u].w << 3));
            ae += (p0 == lv[u].x ? (1u << (p0 << 3)) : 0u)
                + (p1 == lv[u].y ? (1u << (p1 << 3)) : 0u)
                + (p2 == lv[u].z ? (1u << (p2 << 3)) : 0u)
                + (p3 == lv[u].w ? (1u << (p3 << 3)) : 0u);
        }
        // max 8*4 = 32 per 8-bit field — no overflow possible; flush once per batch
        #pragma unroll
        for (int c = 0; c < 4; c++) {
            fp[c] += (ap >> (8 * c)) & 0xFFu;
            fl[c] += (al >> (8 * c)) & 0xFFu;
            fe[c] += (ae >> (8 * c)) & 0xFFu;
        }
    }

    // ---- Vector remainder (no dynamic indexing: pack then flush) ----
    for (; i < n4; i += stride) {
        float4 pv = __ldcg(&preds4[i]);
        int4   lv = __ldcg(&labels4[i]);
        int p0 = (int)pv.x, p1 = (int)pv.y, p2 = (int)pv.z, p3 = (int)pv.w;
        unsigned int ap = (1u << (p0 << 3)) + (1u << (p1 << 3))
                        + (1u << (p2 << 3)) + (1u << (p3 << 3));
        unsigned int al = (1u << (lv.x << 3)) + (1u << (lv.y << 3))
                        + (1u << (lv.z << 3)) + (1u << (lv.w << 3));
        unsigned int ae = (p0 == lv.x ? (1u << (p0 << 3)) : 0u)
                        + (p1 == lv.y ? (1u << (p1 << 3)) : 0u)
                        + (p2 == lv.z ? (1u << (p2 << 3)) : 0u)
                        + (p3 == lv.w ? (1u << (p3 << 3)) : 0u);
        #pragma unroll
        for (int c = 0; c < 4; c++) {
            fp[c] += (ap >> (8 * c)) & 0xFFu;
            fl[c] += (al >> (8 * c)) & 0xFFu;
            fe[c] += (ae >> (8 * c)) & 0xFFu;
        }
    }

    // ---- Scalar tail (n not multiple of 4) ----
    for (long long j = n4 * 4 + tid; j < n; j += stride) {
        int p = (int)preds[j];
        int l = labels[j];
        unsigned int ap = 1u << (p << 3);
        unsigned int al = 1u << (l << 3);
        unsigned int ae = (p == l) ? ap : 0u;
        #pragma unroll
        for (int c = 0; c < 4; c++) {
            fp[c] += (ap >> (8 * c)) & 0xFFu;
            fl[c] += (al >> (8 * c)) & 0xFFu;
            fe[c] += (ae >> (8 * c)) & 0xFFu;
        }
    }

    // ---- Warp-level reduction of the 12 counters ----
    #pragma unroll
    for (int off = 16; off > 0; off >>= 1) {
        #pragma unroll
        for (int c = 0; c < 4; c++) {
            fp[c] += __shfl_down_sync(0xFFFFFFFFu, fp[c], off);
            fl[c] += __shfl_down_sync(0xFFFFFFFFu, fl[c], off);
            fe[c] += __shfl_down_sync(0xFFFFFFFFu, fe[c], off);
        }
    }

    __shared__ unsigned int s[12];
    __shared__ bool s_last;
    if (threadIdx.x < 12) s[threadIdx.x] = 0u;
    __syncthreads();

    if ((threadIdx.x & 31) == 0) {
        #pragma unroll
        for (int c = 0; c < 4; c++) {
            atomicAdd(&s[c],     fp[c]);
            atomicAdd(&s[4 + c], fl[c]);
            atomicAdd(&s[8 + c], fe[c]);
        }
    }
    __syncthreads();

    // ---- Publish this block's partials (plain stores, no contention) ----
    if (threadIdx.x < 12)
        g_partials[threadIdx.x * NBLK + blockIdx.x] = s[threadIdx.x];

    __threadfence();
    __syncthreads();

    if (threadIdx.x == 0) {
        unsigned int old = atomicAdd(&g_ticket, 1u);
        s_last = (old == (unsigned int)(NBLK - 1));
    }
    __syncthreads();

    // ---- Last block reduces all partials and writes the output ----
    if (s_last) {
        unsigned int loc[12];
        #pragma unroll
        for (int c = 0; c < 12; c++) loc[c] = 0u;

        for (int j = threadIdx.x; j < NBLK; j += NTHR) {
            #pragma unroll
            for (int c = 0; c < 12; c++)
                loc[c] += __ldcg(&g_partials[c * NBLK + j]);
        }

        #pragma unroll
        for (int off = 16; off > 0; off >>= 1) {
            #pragma unroll
            for (int c = 0; c < 12; c++)
                loc[c] += __shfl_down_sync(0xFFFFFFFFu, loc[c], off);
        }

        __shared__ unsigned int s_tot[12];
        if (threadIdx.x < 12) s_tot[threadIdx.x] = 0u;
        __syncthreads();
        if ((threadIdx.x & 31) == 0) {
            #pragma unroll
            for (int c = 0; c < 12; c++) atomicAdd(&s_tot[c], loc[c]);
        }
        __syncthreads();

        if (threadIdx.x < 4) {
            int c = threadIdx.x;
            float inter = (float)s_tot[8 + c];
            float uni   = (float)s_tot[c] + (float)s_tot[4 + c] - inter;
            float iou   = (uni == 0.0f) ? 1.0f : (inter / uni);
            out[c] = 1.0f - 100.0f * iou;
        }
        if (threadIdx.x == 0)
            atomicExch(&g_ticket, 0u);   // reset for the next graph replay
    }
}

extern "C" void kernel_launch(void* const* d_in, const int* in_sizes, int n_in,
                              void* d_out, int out_size)
{
    const float* preds  = (const float*)d_in[0];
    const int*   labels = (const int*)d_in[1];
    float*       out    = (float*)d_out;

    long long n  = (long long)in_sizes[0];
    long long n4 = n >> 2;

    iou_fused_kernel<<<NBLK, NTHR>>>(
        (const float4*)preds, (const int4*)labels, n4, preds, labels, n, out);
}

// round 10
// speedup vs baseline: 1.1738x; 1.1220x over previous
#include <cuda_runtime.h>

#define NTHR 256
#define MAXBLK 2048

// Per-block partials, SoA: g_partials[c*MAXBLK + block] for c in 0..11
// [0..3] = count(pred==c), [4..7] = count(label==c), [8..11] = count(pred==label==c)
__device__ unsigned int g_partials[12 * MAXBLK];
__device__ unsigned int g_ticket;   // zero-init at module load; reset by last block each run

__global__ __launch_bounds__(NTHR, 6) void iou_fused_kernel(
    const float4* __restrict__ preds4,
    const int4*   __restrict__ labels4,
    long long n4,
    const float*  __restrict__ preds,
    const int*    __restrict__ labels,
    long long n,
    float* __restrict__ out)
{
    const long long tid    = (long long)blockIdx.x * NTHR + threadIdx.x;
    const long long stride = (long long)gridDim.x * NTHR;

    // Full-width counters — only touched at (rare) flushes and epilogue.
    unsigned int fp[4] = {0u,0u,0u,0u};
    unsigned int fl[4] = {0u,0u,0u,0u};
    unsigned int fe[4] = {0u,0u,0u,0u};

    // Packed 8-bit-per-class accumulators: the ONLY mainloop-resident counters.
    unsigned int ap = 0u, al = 0u, ae = 0u;
    int pend = 0;   // vec-iters since last flush; each adds <=4 per 8-bit field

#define FLUSH_PACKED() do {                                   \
        _Pragma("unroll")                                     \
        for (int c = 0; c < 4; c++) {                         \
            fp[c] += (ap >> (8*c)) & 0xFFu;                   \
            fl[c] += (al >> (8*c)) & 0xFFu;                   \
            fe[c] += (ae >> (8*c)) & 0xFFu;                   \
        }                                                     \
        ap = 0u; al = 0u; ae = 0u; pend = 0;                  \
    } while (0)

    long long i = tid;

    // ---- Mainloop: 4 vec4-pairs per batch (8 LDG.128 front-batched, 32 regs) ----
    for (; i + 3 * stride < n4; i += 4 * stride) {
        float4 pv[4];
        int4   lv[4];
        #pragma unroll
        for (int u = 0; u < 4; u++) pv[u] = __ldcg(&preds4[i + u * stride]);
        #pragma unroll
        for (int u = 0; u < 4; u++) lv[u] = __ldcg(&labels4[i + u * stride]);

        #pragma unroll
        for (int u = 0; u < 4; u++) {
            int p0 = (int)pv[u].x, p1 = (int)pv[u].y,
                p2 = (int)pv[u].z, p3 = (int)pv[u].w;
            ap += (1u << (p0 << 3)) + (1u << (p1 << 3))
                + (1u << (p2 << 3)) + (1u << (p3 << 3));
            al += (1u << (lv[u].x << 3)) + (1u << (lv[u].y << 3))
                + (1u << (lv[u].z << 3)) + (1u << (lv[u].w << 3));
            ae += (p0 == lv[u].x ? (1u << (p0 << 3)) : 0u)
                + (p1 == lv[u].y ? (1u << (p1 << 3)) : 0u)
                + (p2 == lv[u].z ? (1u << (p2 << 3)) : 0u)
                + (p3 == lv[u].w ? (1u << (p3 << 3)) : 0u);
        }
        pend += 4;
        // max at check: 60 vec-iters * 4 = 240 < 255 — no 8-bit overflow possible
        if (pend >= 60) FLUSH_PACKED();
    }

    // ---- Vector remainder ----
    for (; i < n4; i += stride) {
        float4 pv = __ldcg(&preds4[i]);
        int4   lv = __ldcg(&labels4[i]);
        int p0 = (int)pv.x, p1 = (int)pv.y, p2 = (int)pv.z, p3 = (int)pv.w;
        ap += (1u << (p0 << 3)) + (1u << (p1 << 3))
            + (1u << (p2 << 3)) + (1u << (p3 << 3));
        al += (1u << (lv.x << 3)) + (1u << (lv.y << 3))
            + (1u << (lv.z << 3)) + (1u << (lv.w << 3));
        ae += (p0 == lv.x ? (1u << (p0 << 3)) : 0u)
            + (p1 == lv.y ? (1u << (p1 << 3)) : 0u)
            + (p2 == lv.z ? (1u << (p2 << 3)) : 0u)
            + (p3 == lv.w ? (1u << (p3 << 3)) : 0u);
        if (++pend >= 60) FLUSH_PACKED();
    }

    // ---- Scalar tail (n not multiple of 4) ----
    for (long long j = n4 * 4 + tid; j < n; j += stride) {
        int p = (int)preds[j];
        int l = labels[j];
        ap += 1u << (p << 3);
        al += 1u << (l << 3);
        ae += (p == l) ? (1u << (p << 3)) : 0u;
        if (++pend >= 60) FLUSH_PACKED();
    }
    FLUSH_PACKED();
#undef FLUSH_PACKED

    // ---- Warp-level reduction via REDUX ----
    #pragma unroll
    for (int c = 0; c < 4; c++) {
        fp[c] = __reduce_add_sync(0xFFFFFFFFu, fp[c]);
        fl[c] = __reduce_add_sync(0xFFFFFFFFu, fl[c]);
        fe[c] = __reduce_add_sync(0xFFFFFFFFu, fe[c]);
    }

    __shared__ unsigned int s[12];
    __shared__ bool s_last;
    if (threadIdx.x < 12) s[threadIdx.x] = 0u;
    __syncthreads();

    if ((threadIdx.x & 31) == 0) {
        #pragma unroll
        for (int c = 0; c < 4; c++) {
            atomicAdd(&s[c],     fp[c]);
            atomicAdd(&s[4 + c], fl[c]);
            atomicAdd(&s[8 + c], fe[c]);
        }
    }
    __syncthreads();

    // ---- Publish this block's partials (plain stores, no contention) ----
    if (threadIdx.x < 12)
        g_partials[threadIdx.x * MAXBLK + blockIdx.x] = s[threadIdx.x];

    __threadfence();
    __syncthreads();

    if (threadIdx.x == 0) {
        unsigned int old = atomicAdd(&g_ticket, 1u);
        s_last = (old == gridDim.x - 1u);
    }
    __syncthreads();

    // ---- Last block reduces all partials and writes the output ----
    if (s_last) {
        unsigned int loc[12];
        #pragma unroll
        for (int c = 0; c < 12; c++) loc[c] = 0u;

        for (unsigned int j = threadIdx.x; j < gridDim.x; j += NTHR) {
            #pragma unroll
            for (int c = 0; c < 12; c++)
                loc[c] += __ldcg(&g_partials[c * MAXBLK + j]);
        }

        #pragma unroll
        for (int c = 0; c < 12; c++)
            loc[c] = __reduce_add_sync(0xFFFFFFFFu, loc[c]);

        __shared__ unsigned int s_tot[12];
        if (threadIdx.x < 12) s_tot[threadIdx.x] = 0u;
        __syncthreads();
        if ((threadIdx.x & 31) == 0) {
            #pragma unroll
            for (int c = 0; c < 12; c++) atomicAdd(&s_tot[c], loc[c]);
        }
        __syncthreads();

        if (threadIdx.x < 4) {
            int c = threadIdx.x;
            float inter = (float)s_tot[8 + c];
            float uni   = (float)s_tot[c] + (float)s_tot[4 + c] - inter;
            float iou   = (uni == 0.0f) ? 1.0f : (inter / uni);
            out[c] = 1.0f - 100.0f * iou;
        }
        if (threadIdx.x == 0)
            atomicExch(&g_ticket, 0u);   // reset for the next graph replay
    }
}

extern "C" void kernel_launch(void* const* d_in, const int* in_sizes, int n_in,
                              void* d_out, int out_size)
{
    const float* preds  = (const float*)d_in[0];
    const int*   labels = (const int*)d_in[1];
    float*       out    = (float*)d_out;

    long long n  = (long long)in_sizes[0];
    long long n4 = n >> 2;

    // Single-wave persistent grid: 6 blocks per SM (matches __launch_bounds__).
    static int nsm = 0;
    if (nsm == 0) {
        int dev = 0;
        cudaGetDevice(&dev);
        cudaDeviceGetAttribute(&nsm, cudaDevAttrMultiProcessorCount, dev);
        if (nsm <= 0) nsm = 148;
    }
    int nblk = 6 * nsm;
    if (nblk > MAXBLK) nblk = MAXBLK;

    iou_fused_kernel<<<nblk, NTHR>>>(
        (const float4*)preds, (const int4*)labels, n4, preds, labels, n, out);
}

// round 12
// speedup vs baseline: 1.1786x; 1.0041x over previous
#include <cuda_runtime.h>
#include <cstdint>

#define NTHR 256
#define NSTAGES 2
#define STAGE_ELEMS 2048                    // elements per stage per tensor
#define STAGE_BYTES (STAGE_ELEMS * 4)       // 8 KB per tensor per stage
#define VEC_PER_THREAD (STAGE_ELEMS / 4 / NTHR)   // 2 float4 per thread per stage
#define MAXBLK 2048

// Per-block partials, SoA: g_partials[c*MAXBLK + block], c in 0..11
// [0..3]=count(pred==c) [4..7]=count(label==c) [8..11]=count(pred==label==c)
__device__ unsigned int g_partials[12 * MAXBLK];
__device__ unsigned int g_ticket;   // zero-init at load; reset by last block each run

// ---------------- mbarrier / bulk-copy helpers ----------------
#define MB_INIT(addr, cnt) \
    asm volatile("mbarrier.init.shared.b64 [%0], %1;" :: "r"(addr), "r"(cnt) : "memory")
#define MB_EXPECT_TX(addr, tx) \
    asm volatile("mbarrier.arrive.expect_tx.shared.b64 _, [%0], %1;" :: "r"(addr), "r"(tx) : "memory")
#define MB_ARRIVE(addr) \
    asm volatile("mbarrier.arrive.shared.b64 _, [%0];" :: "r"(addr) : "memory")
#define MB_WAIT(addr, ph) do {                                                   \
    unsigned int _done;                                                          \
    asm volatile("{\n\t.reg .pred p;\n\t"                                        \
        "mbarrier.try_wait.parity.acquire.cta.shared::cta.b64 p, [%1], %2;\n\t"  \
        "selp.b32 %0, 1, 0, p;\n\t}"                                             \
        : "=r"(_done) : "r"(addr), "r"(ph) : "memory");                          \
    while (!_done) {                                                             \
        asm volatile("{\n\t.reg .pred p;\n\t"                                    \
            "mbarrier.try_wait.parity.acquire.cta.shared::cta.b64 p, [%1], %2, 0x989680;\n\t" \
            "selp.b32 %0, 1, 0, p;\n\t}"                                         \
            : "=r"(_done) : "r"(addr), "r"(ph) : "memory");                      \
    }                                                                            \
} while (0)
#define BULK_G2S(dst, src, bytes, bar) \
    asm volatile("cp.async.bulk.shared::cluster.global.mbarrier::complete_tx::bytes " \
                 "[%0], [%1], %2, [%3];"                                          \
                 :: "r"(dst), "l"(src), "r"(bytes), "r"(bar) : "memory")

__device__ __forceinline__ unsigned int smem_u32(const void* p) {
    return (unsigned int)__cvta_generic_to_shared(p);
}

__global__ __launch_bounds__(NTHR, 6) void iou_tma_kernel(
    const float* __restrict__ preds,
    const int*   __restrict__ labels,
    long long n,
    float* __restrict__ out)
{
    __shared__ __align__(128) unsigned char sm_pred[NSTAGES][STAGE_BYTES];
    __shared__ __align__(128) unsigned char sm_lab [NSTAGES][STAGE_BYTES];
    __shared__ __align__(8) unsigned long long mb_full [NSTAGES];
    __shared__ __align__(8) unsigned long long mb_empty[NSTAGES];
    __shared__ unsigned int s[12];
    __shared__ bool s_last;

    const int tid = threadIdx.x;
    const unsigned int G = gridDim.x;
    const long long total_stages = n / STAGE_ELEMS;

    if (tid == 0) {
        #pragma unroll
        for (int i = 0; i < NSTAGES; i++) {
            MB_INIT(smem_u32(&mb_full[i]),  1u);
            MB_INIT(smem_u32(&mb_empty[i]), (unsigned int)NTHR);
        }
        asm volatile("fence.proxy.async.shared::cta;" ::: "memory");
    }
    if (tid < 12) s[tid] = 0u;
    __syncthreads();

    // ---- Prologue: prime all stages (fresh empty barriers — no wait needed) ----
    if (tid == 0) {
        #pragma unroll
        for (int j = 0; j < NSTAGES; j++) {
            long long st = (long long)blockIdx.x + (long long)j * G;
            if (st < total_stages) {
                unsigned int bar = smem_u32(&mb_full[j]);
                MB_EXPECT_TX(bar, 2u * STAGE_BYTES);
                BULK_G2S(smem_u32(&sm_pred[j][0]), preds  + st * STAGE_ELEMS,
                         (unsigned int)STAGE_BYTES, bar);
                BULK_G2S(smem_u32(&sm_lab[j][0]),  labels + st * STAGE_ELEMS,
                         (unsigned int)STAGE_BYTES, bar);
            }
        }
    }

    // Full-width counters (flushed rarely) + packed 8-bit accumulators.
    unsigned int fp[4] = {0u,0u,0u,0u};
    unsigned int fl[4] = {0u,0u,0u,0u};
    unsigned int fe[4] = {0u,0u,0u,0u};
    unsigned int ap = 0u, al = 0u, ae = 0u;
    int pend = 0;

#define FLUSH_PACKED() do {                                   \
        _Pragma("unroll")                                     \
        for (int c = 0; c < 4; c++) {                         \
            fp[c] += (ap >> (8*c)) & 0xFFu;                   \
            fl[c] += (al >> (8*c)) & 0xFFu;                   \
            fe[c] += (ae >> (8*c)) & 0xFFu;                   \
        }                                                     \
        ap = 0u; al = 0u; ae = 0u; pend = 0;                  \
    } while (0)

    // ---- Pipelined mainloop ----
    {
        int slot = 0, phase = 0;
        for (long long k = 0; ; k++) {
            long long st = (long long)blockIdx.x + k * G;
            if (st >= total_stages) break;

            MB_WAIT(smem_u32(&mb_full[slot]), (unsigned int)phase);

            const float4* pp = (const float4*)&sm_pred[slot][0];
            const int4*   ll = (const int4*)&sm_lab[slot][0];
            #pragma unroll
            for (int v = 0; v < VEC_PER_THREAD; v++) {
                float4 pv = pp[v * NTHR + tid];
                int4   lv = ll[v * NTHR + tid];
                // magic-number float->int: bits(x + 1.5*2^23) & 3  (x in 0..3)
                int p0 = (int)(__float_as_uint(pv.x + 12582912.0f) & 3u);
                int p1 = (int)(__float_as_uint(pv.y + 12582912.0f) & 3u);
                int p2 = (int)(__float_as_uint(pv.z + 12582912.0f) & 3u);
                int p3 = (int)(__float_as_uint(pv.w + 12582912.0f) & 3u);
                ap += (1u << (p0 << 3)) + (1u << (p1 << 3))
                    + (1u << (p2 << 3)) + (1u << (p3 << 3));
                al += (1u << (lv.x << 3)) + (1u << (lv.y << 3))
                    + (1u << (lv.z << 3)) + (1u << (lv.w << 3));
                ae += (p0 == lv.x ? (1u << (p0 << 3)) : 0u)
                    + (p1 == lv.y ? (1u << (p1 << 3)) : 0u)
                    + (p2 == lv.z ? (1u << (p2 << 3)) : 0u)
                    + (p3 == lv.w ? (1u << (p3 << 3)) : 0u);
            }
            pend += VEC_PER_THREAD;
            if (pend >= 60) FLUSH_PACKED();   // max 60*4=240 < 255: no overflow

            MB_ARRIVE(smem_u32(&mb_empty[slot]));

            if (tid == 0) {
                long long nst = st + (long long)NSTAGES * G;
                if (nst < total_stages) {
                    // wait for all 256 consumer arrivals of this iteration
                    MB_WAIT(smem_u32(&mb_empty[slot]), (unsigned int)phase);
                    unsigned int bar = smem_u32(&mb_full[slot]);
                    MB_EXPECT_TX(bar, 2u * STAGE_BYTES);
                    BULK_G2S(smem_u32(&sm_pred[slot][0]), preds  + nst * STAGE_ELEMS,
                             (unsigned int)STAGE_BYTES, bar);
                    BULK_G2S(smem_u32(&sm_lab[slot][0]),  labels + nst * STAGE_ELEMS,
                             (unsigned int)STAGE_BYTES, bar);
                }
            }

            if (++slot == NSTAGES) { slot = 0; phase ^= 1; }
        }
    }
    FLUSH_PACKED();

    // ---- Scalar tail (elements beyond full stages), direct from global ----
    for (long long j = total_stages * STAGE_ELEMS + (long long)blockIdx.x * NTHR + tid;
         j < n; j += (long long)G * NTHR) {
        int p = (int)preds[j];
        int l = labels[j];
        ap += 1u << (p << 3);
        al += 1u << (l << 3);
        ae += (p == l) ? (1u << (p << 3)) : 0u;
        if (++pend >= 60) FLUSH_PACKED();
    }
    FLUSH_PACKED();
#undef FLUSH_PACKED

    // ---- Warp reduction via REDUX ----
    #pragma unroll
    for (int c = 0; c < 4; c++) {
        fp[c] = __reduce_add_sync(0xFFFFFFFFu, fp[c]);
        fl[c] = __reduce_add_sync(0xFFFFFFFFu, fl[c]);
        fe[c] = __reduce_add_sync(0xFFFFFFFFu, fe[c]);
    }

    __syncthreads();   // s[] zeroed earlier; ensure visible & pipeline fully drained
    if ((tid & 31) == 0) {
        #pragma unroll
        for (int c = 0; c < 4; c++) {
            atomicAdd(&s[c],     fp[c]);
            atomicAdd(&s[4 + c], fl[c]);
            atomicAdd(&s[8 + c], fe[c]);
        }
    }
    __syncthreads();

    if (tid < 12)
        g_partials[tid * MAXBLK + blockIdx.x] = s[tid];

    __threadfence();
    __syncthreads();

    if (tid == 0) {
        unsigned int old = atomicAdd(&g_ticket, 1u);
        s_last = (old == gridDim.x - 1u);
    }
    __syncthreads();

    if (s_last) {
        unsigned int loc[12];
        #pragma unroll
        for (int c = 0; c < 12; c++) loc[c] = 0u;

        for (unsigned int j = tid; j < gridDim.x; j += NTHR) {
            #pragma unroll
            for (int c = 0; c < 12; c++)
                loc[c] += __ldcg(&g_partials[c * MAXBLK + j]);
        }
        #pragma unroll
        for (int c = 0; c < 12; c++)
            loc[c] = __reduce_add_sync(0xFFFFFFFFu, loc[c]);

        __shared__ unsigned int s_tot[12];
        if (tid < 12) s_tot[tid] = 0u;
        __syncthreads();
        if ((tid & 31) == 0) {
            #pragma unroll
            for (int c = 0; c < 12; c++) atomicAdd(&s_tot[c], loc[c]);
        }
        __syncthreads();

        if (tid < 4) {
            int c = tid;
            float inter = (float)s_tot[8 + c];
            float uni   = (float)s_tot[c] + (float)s_tot[4 + c] - inter;
            float iou   = (uni == 0.0f) ? 1.0f : (inter / uni);
            out[c] = 1.0f - 100.0f * iou;
        }
        if (tid == 0)
            atomicExch(&g_ticket, 0u);   // reset for next graph replay
    }
}

extern "C" void kernel_launch(void* const* d_in, const int* in_sizes, int n_in,
                              void* d_out, int out_size)
{
    const float* preds  = (const float*)d_in[0];
    const int*   labels = (const int*)d_in[1];
    float*       out    = (float*)d_out;

    long long n = (long long)in_sizes[0];

    static int nsm = 0;
    if (nsm == 0) {
        int dev = 0;
        cudaGetDevice(&dev);
        cudaDeviceGetAttribute(&nsm, cudaDevAttrMultiProcessorCount, dev);
        if (nsm <= 0) nsm = 148;
    }
    int nblk = 6 * nsm;          // single wave at 6 CTAs/SM (33 KB smem each)
    if (nblk > MAXBLK) nblk = MAXBLK;

    iou_tma_kernel<<<nblk, NTHR>>>(preds, labels, n, out);
}